// round 3
// baseline (speedup 1.0000x reference)
#include <cuda_runtime.h>
#include <math.h>

#define NN 40000
#define NE 640000

// ---- constants ----
#define RSQRT32f 0.1767766952966368811f   // 1/sqrt(32)
#define RSQRT8f  0.3535533905932737622f   // 1/sqrt(8)
#define SILUNf   1.6791767923989418f
#define RSQRT3f  0.5773502691896257645f
#define SCALE2f  0.03125f                 // (1/sqrt(16)) / sqrt(64) = 0.25/8

// ---- device scratch (static, allocation-free) ----
__device__ float g_feat [NN * 128];   // [s(32) | v(32x3, i fastest)]
__device__ float g_acc_s[NN * 64];    // ns accumulator
__device__ float g_acc_v[NN * 192];   // nv accumulator (u*3+i)

__device__ __forceinline__ void red4(float* p, float a, float b, float c, float d) {
    asm volatile("red.global.add.v4.f32 [%0], {%1,%2,%3,%4};"
                 :: "l"(p), "f"(a), "f"(b), "f"(c), "f"(d) : "memory");
}

// ============================================================
// Kernel 0: zero the accumulators (10.24M floats)
// ============================================================
__global__ void zero_acc() {
    const float4 z = make_float4(0.f, 0.f, 0.f, 0.f);
    float4* a = reinterpret_cast<float4*>(g_acc_s);   // 640000 float4
    float4* b = reinterpret_cast<float4*>(g_acc_v);   // 1920000 float4
    int idx = blockIdx.x * blockDim.x + threadIdx.x;
    int stride = gridDim.x * blockDim.x;
    for (int i = idx; i < NN * 64 / 4;  i += stride) a[i] = z;
    for (int i = idx; i < NN * 192 / 4; i += stride) b[i] = z;
}

// ============================================================
// Kernel 1: node lin1  (s = s@W1s/sqrt32, v = v@W1v/sqrt32)
// one warp per node, 8 nodes / 256-thread block
// ============================================================
__global__ __launch_bounds__(256) void node_lin1(
    const float* __restrict__ node_input,
    const float* __restrict__ w1s,
    const float* __restrict__ w1v)
{
    __shared__ float sWs[32 * 32];
    __shared__ float sWv[32 * 32];
    __shared__ float sRow[8][128];

    int t = threadIdx.x;
    for (int i = t; i < 1024; i += 256) {
        sWs[i] = w1s[i] * RSQRT32f;
        sWv[i] = w1v[i] * RSQRT32f;
    }
    int warp = t >> 5, lane = t & 31;
    int n = blockIdx.x * 8 + warp;

    const float4* rowp = reinterpret_cast<const float4*>(node_input + (size_t)n * 128);
    *reinterpret_cast<float4*>(&sRow[warp][lane * 4]) = rowp[lane];
    __syncthreads();

    const float* r = sRow[warp];
    float s = 0.f, v0 = 0.f, v1 = 0.f, v2 = 0.f;
#pragma unroll
    for (int u = 0; u < 32; u++) {
        float ws = sWs[u * 32 + lane];
        float wv = sWv[u * 32 + lane];
        s  += r[u] * ws;
        v0 += r[32 + u * 3 + 0] * wv;
        v1 += r[32 + u * 3 + 1] * wv;
        v2 += r[32 + u * 3 + 2] * wv;
    }
    float* o = g_feat + (size_t)n * 128;
    o[lane] = s;
    o[32 + lane * 3 + 0] = v0;
    o[32 + lane * 3 + 1] = v1;
    o[32 + lane * 3 + 2] = v2;
}

// ============================================================
// Kernel 2: per-edge MLP (fused 2-layer GEMM) + tensor-product
//           messages + vectorized scatter-add to destination
// 64 edges per 256-thread block; dynamic shared 53504 B.
// Shared layout (floats):
//   [0    : 512 )  W1 (scaled)
//   [512  : 1088)  X  (64 x 9, padded)
//   [1088 : 9280)  W2 (scaled)
//   [9280 :13376)  H  (c-major: sH[c*64+e])
//   Wout (64x128 = 8192 floats) overlays [0:8192) after GEMM2 sync.
// ============================================================
__global__ __launch_bounds__(256) void edge_kernel(
    const int*   __restrict__ esrc,
    const int*   __restrict__ edst,
    const float* __restrict__ eattr,
    const float* __restrict__ escal,
    const float* __restrict__ fw1,
    const float* __restrict__ fw2)
{
    extern __shared__ __align__(16) float sm[];
    float* sW1   = sm;
    float* sX    = sm + 512;
    float* sW2   = sm + 1088;
    float* sH    = sm + 9280;
    float* sWout = sm;            // reuse after GEMM2

    const int t = threadIdx.x;
    const int eBase = blockIdx.x * 64;

    // ---- stage weights + inputs ----
    for (int i = t; i < 512; i += 256)  sW1[i] = fw1[i] * RSQRT8f;
    for (int i = t; i < 8192; i += 256) sW2[i] = fw2[i] * 0.125f;
    for (int i = t; i < 512; i += 256) {
        int e = i >> 3, k = i & 7;
        sX[e * 9 + k] = escal[(size_t)eBase * 8 + i];
    }
    __syncthreads();

    // ---- GEMM1 (64x8 @ 8x64) + silu, store H c-major ----
    {
        int e  = t & 63;
        int c0 = (t >> 6) * 16;
        float x[8];
#pragma unroll
        for (int k = 0; k < 8; k++) x[k] = sX[e * 9 + k];
#pragma unroll
        for (int cc = 0; cc < 16; cc++) {
            int c = c0 + cc;
            float a = 0.f;
#pragma unroll
            for (int k = 0; k < 8; k++) a += x[k] * sW1[k * 64 + c];
            float sg = 1.f / (1.f + __expf(-a));
            sH[c * 64 + e] = a * sg * SILUNf;
        }
    }
    __syncthreads();

    // ---- GEMM2 (64x64 @ 64x128), 4x8 micro-tile per thread ----
    float acc[4][8];
#pragma unroll
    for (int i = 0; i < 4; i++)
#pragma unroll
        for (int j = 0; j < 8; j++) acc[i][j] = 0.f;

    const int ej = (t & 15) * 4;
    const int cj = (t >> 4) * 8;
#pragma unroll 8
    for (int c = 0; c < 64; c++) {
        float4 h4 = *reinterpret_cast<const float4*>(sH  + c * 64 + ej);
        float4 wa = *reinterpret_cast<const float4*>(sW2 + c * 128 + cj);
        float4 wb = *reinterpret_cast<const float4*>(sW2 + c * 128 + cj + 4);
        float hh[4] = { h4.x, h4.y, h4.z, h4.w };
        float ww[8] = { wa.x, wa.y, wa.z, wa.w, wb.x, wb.y, wb.z, wb.w };
#pragma unroll
        for (int i = 0; i < 4; i++)
#pragma unroll
            for (int j = 0; j < 8; j++)
                acc[i][j] += hh[i] * ww[j];
    }
    __syncthreads();   // all reads of sW1/sX/sW2/sH done

    // ---- spill W to shared (overlays old region) ----
#pragma unroll
    for (int i = 0; i < 4; i++) {
        *reinterpret_cast<float4*>(sWout + (ej + i) * 128 + cj) =
            make_float4(acc[i][0], acc[i][1], acc[i][2], acc[i][3]);
        *reinterpret_cast<float4*>(sWout + (ej + i) * 128 + cj + 4) =
            make_float4(acc[i][4], acc[i][5], acc[i][6], acc[i][7]);
    }
    __syncthreads();

    // ---- tensor-product messages + scatter-add ----
    // 4 threads per edge, each handles 8 consecutive mul-indices
    const int le = t >> 2;           // local edge 0..63
    const int p  = t & 3;
    const int m0 = p * 8;
    const int e  = eBase + le;

    const int srcn = esrc[e];
    const int dstn = edst[e];
    float4 ea = *reinterpret_cast<const float4*>(eattr + (size_t)e * 4);
    const float es  = ea.x;
    const float ev0 = ea.y, ev1 = ea.z, ev2 = ea.w;

    const float* feat = g_feat + (size_t)srcn * 128;
    float se[8];
    *reinterpret_cast<float4*>(&se[0]) = *reinterpret_cast<const float4*>(feat + m0);
    *reinterpret_cast<float4*>(&se[4]) = *reinterpret_cast<const float4*>(feat + m0 + 4);
    float ve[24];
#pragma unroll
    for (int q = 0; q < 6; q++)
        *reinterpret_cast<float4*>(&ve[q * 4]) =
            *reinterpret_cast<const float4*>(feat + 32 + m0 * 3 + q * 4);

    const float* Wp = sWout + le * 128 + m0;
    float w0[8], w1[8], w2[8], w3[8];
    *reinterpret_cast<float4*>(&w0[0]) = *reinterpret_cast<const float4*>(Wp + 0);
    *reinterpret_cast<float4*>(&w0[4]) = *reinterpret_cast<const float4*>(Wp + 4);
    *reinterpret_cast<float4*>(&w1[0]) = *reinterpret_cast<const float4*>(Wp + 32);
    *reinterpret_cast<float4*>(&w1[4]) = *reinterpret_cast<const float4*>(Wp + 36);
    *reinterpret_cast<float4*>(&w2[0]) = *reinterpret_cast<const float4*>(Wp + 64);
    *reinterpret_cast<float4*>(&w2[4]) = *reinterpret_cast<const float4*>(Wp + 68);
    *reinterpret_cast<float4*>(&w3[0]) = *reinterpret_cast<const float4*>(Wp + 96);
    *reinterpret_cast<float4*>(&w3[4]) = *reinterpret_cast<const float4*>(Wp + 100);

    float s0[8], s1[8], v0a[24], v1a[24];
#pragma unroll
    for (int j = 0; j < 8; j++) {
        float sej = se[j];
        s0[j] = w0[j] * sej * es;
        float dotp = ve[j * 3] * ev0 + ve[j * 3 + 1] * ev1 + ve[j * 3 + 2] * ev2;
        s1[j] = w3[j] * dotp * RSQRT3f;
        float a = w1[j] * sej;
        v0a[j * 3 + 0] = a * ev0;
        v0a[j * 3 + 1] = a * ev1;
        v0a[j * 3 + 2] = a * ev2;
        float b = w2[j] * es;
        v1a[j * 3 + 0] = b * ve[j * 3 + 0];
        v1a[j * 3 + 1] = b * ve[j * 3 + 1];
        v1a[j * 3 + 2] = b * ve[j * 3 + 2];
    }

    float* as = g_acc_s + (size_t)dstn * 64 + m0;
    red4(as,      s0[0], s0[1], s0[2], s0[3]);
    red4(as + 4,  s0[4], s0[5], s0[6], s0[7]);
    red4(as + 32, s1[0], s1[1], s1[2], s1[3]);
    red4(as + 36, s1[4], s1[5], s1[6], s1[7]);

    float* av = g_acc_v + (size_t)dstn * 192 + m0 * 3;
#pragma unroll
    for (int q = 0; q < 6; q++)
        red4(av + q * 4, v0a[q * 4], v0a[q * 4 + 1], v0a[q * 4 + 2], v0a[q * 4 + 3]);
#pragma unroll
    for (int q = 0; q < 6; q++)
        red4(av + 96 + q * 4, v1a[q * 4], v1a[q * 4 + 1], v1a[q * 4 + 2], v1a[q * 4 + 3]);
}

// ============================================================
// Kernel 3: node lin2 + final concat output
// one warp per node, 8 nodes / 256-thread block
// ============================================================
__global__ __launch_bounds__(256) void node_lin2(
    const float* __restrict__ w2s,
    const float* __restrict__ w2v,
    float* __restrict__ out)
{
    __shared__ float sWs[64 * 32];
    __shared__ float sWv[64 * 32];
    __shared__ float sRow[8][256];

    int t = threadIdx.x;
    for (int i = t; i < 2048; i += 256) {
        sWs[i] = w2s[i] * SCALE2f;
        sWv[i] = w2v[i] * SCALE2f;
    }
    int warp = t >> 5, lane = t & 31;
    int n = blockIdx.x * 8 + warp;

    const float4* ap = reinterpret_cast<const float4*>(g_acc_s + (size_t)n * 64);
    const float4* vp = reinterpret_cast<const float4*>(g_acc_v + (size_t)n * 192);
    if (lane < 16)
        *reinterpret_cast<float4*>(&sRow[warp][lane * 4]) = ap[lane];
    *reinterpret_cast<float4*>(&sRow[warp][64 + lane * 4]) = vp[lane];
    if (lane < 16)
        *reinterpret_cast<float4*>(&sRow[warp][64 + 128 + lane * 4]) = vp[32 + lane];
    __syncthreads();

    const float* r = sRow[warp];
    float s = 0.f, v0 = 0.f, v1 = 0.f, v2 = 0.f;
#pragma unroll
    for (int u = 0; u < 64; u++) {
        s += r[u] * sWs[u * 32 + lane];
        float wv = sWv[u * 32 + lane];
        v0 += r[64 + u * 3 + 0] * wv;
        v1 += r[64 + u * 3 + 1] * wv;
        v2 += r[64 + u * 3 + 2] * wv;
    }
    float* o = out + (size_t)n * 128;
    o[lane] = s;
    o[32 + lane * 3 + 0] = v0;
    o[32 + lane * 3 + 1] = v1;
    o[32 + lane * 3 + 2] = v2;
}

// ============================================================
// launch
// ============================================================
extern "C" void kernel_launch(void* const* d_in, const int* in_sizes, int n_in,
                              void* d_out, int out_size)
{
    const float* node_input = (const float*)d_in[0];
    // d_in[1] = node_attr (all ones, unused by reference)
    const int*   esrc  = (const int*)d_in[2];
    const int*   edst  = (const int*)d_in[3];
    const float* eattr = (const float*)d_in[4];
    const float* escal = (const float*)d_in[5];
    const float* w1s   = (const float*)d_in[6];
    const float* w1v   = (const float*)d_in[7];
    const float* fw1   = (const float*)d_in[8];
    const float* fw2   = (const float*)d_in[9];
    const float* w2s   = (const float*)d_in[10];
    const float* w2v   = (const float*)d_in[11];
    float* out = (float*)d_out;

    zero_acc<<<2048, 256>>>();
    node_lin1<<<NN / 8, 256>>>(node_input, w1s, w1v);

    const int smem = 13376 * (int)sizeof(float);   // 53504 B
    cudaFuncSetAttribute(edge_kernel, cudaFuncAttributeMaxDynamicSharedMemorySize, smem);
    edge_kernel<<<NE / 64, 256, smem>>>(esrc, edst, eattr, escal, fw1, fw2);

    node_lin2<<<NN / 8, 256>>>(w2s, w2v, out);
}

// round 14
// speedup vs baseline: 1.2948x; 1.2948x over previous
#include <cuda_runtime.h>
#include <cuda_bf16.h>
#include <math.h>

#define NN 40000
#define NE 640000

#define RSQRT32f 0.1767766952966368811f
#define RSQRT8f  0.3535533905932737622f
#define SILUNf   1.6791767923989418f
#define RSQRT3f  0.5773502691896257645f
#define SCALE2f  0.03125f

// ---- device scratch ----
__device__ float g_feat [NN * 128];
__device__ float g_acc_s[NN * 64];
__device__ float g_acc_v[NN * 192];
__device__ __align__(16) unsigned g_w2t_hi[4096];  // [128n x 64k] bf16 pairs, SW128-swizzled
__device__ __align__(16) unsigned g_w2t_lo[4096];

__device__ __forceinline__ void red4(float* p, float a, float b, float c, float d) {
    asm volatile("red.global.add.v4.f32 [%0], {%1,%2,%3,%4};"
                 :: "l"(p), "f"(a), "f"(b), "f"(c), "f"(d) : "memory");
}
__device__ __forceinline__ unsigned smem_u32(const void* p) {
    unsigned a;
    asm("{ .reg .u64 t; cvta.to.shared.u64 t, %1; cvt.u32.u64 %0, t; }" : "=r"(a) : "l"(p));
    return a;
}
__device__ __forceinline__ void ldm4(unsigned* r, unsigned addr) {
    asm volatile("ldmatrix.sync.aligned.m8n8.x4.shared.b16 {%0,%1,%2,%3}, [%4];"
                 : "=r"(r[0]), "=r"(r[1]), "=r"(r[2]), "=r"(r[3]) : "r"(addr));
}
__device__ __forceinline__ void mma_bf16(float* d, const unsigned* a, const unsigned* b) {
    asm volatile("mma.sync.aligned.m16n8k16.row.col.f32.bf16.bf16.f32 "
                 "{%0,%1,%2,%3}, {%4,%5,%6,%7}, {%8,%9}, {%0,%1,%2,%3};"
                 : "+f"(d[0]), "+f"(d[1]), "+f"(d[2]), "+f"(d[3])
                 : "r"(a[0]), "r"(a[1]), "r"(a[2]), "r"(a[3]), "r"(b[0]), "r"(b[1]));
}

#define SW128(off) ((off) ^ (((off) >> 3) & 0x70))

// SMEM layout (bytes); sWout (64x128 f32 = 32768B) overlays [0,32768) after MMA.
#define SM_A_HI 0
#define SM_A_LO 8192
#define SM_B_HI 16384
#define SM_B_LO 32768
#define SM_W1   49152
#define SM_TOTAL 51200

// ============================================================
// zero accumulators
// ============================================================
__global__ void zero_acc() {
    const float4 z = make_float4(0.f, 0.f, 0.f, 0.f);
    float4* a = reinterpret_cast<float4*>(g_acc_s);
    float4* b = reinterpret_cast<float4*>(g_acc_v);
    int idx = blockIdx.x * blockDim.x + threadIdx.x;
    int stride = gridDim.x * blockDim.x;
    for (int i = idx; i < NN * 64 / 4;  i += stride) a[i] = z;
    for (int i = idx; i < NN * 192 / 4; i += stride) b[i] = z;
}

// ============================================================
// prep: W2^T (scaled 1/8) -> bf16 hi/lo, [n][k] rows, SW128 image
// ============================================================
__global__ void prep_w2t(const float* __restrict__ fw2) {
    int idx = blockIdx.x * blockDim.x + threadIdx.x;   // 0..4095
    int n  = idx >> 5;
    int kp = idx & 31;
    int k  = kp * 2;
    float v0 = fw2[(size_t)k * 128 + n] * 0.125f;
    float v1 = fw2[(size_t)(k + 1) * 128 + n] * 0.125f;
    __nv_bfloat16 h0 = __float2bfloat16(v0);
    __nv_bfloat16 h1 = __float2bfloat16(v1);
    __nv_bfloat16 l0 = __float2bfloat16(v0 - __bfloat162float(h0));
    __nv_bfloat16 l1 = __float2bfloat16(v1 - __bfloat162float(h1));
    unsigned hi = (unsigned)__bfloat16_as_ushort(h0) | ((unsigned)__bfloat16_as_ushort(h1) << 16);
    unsigned lo = (unsigned)__bfloat16_as_ushort(l0) | ((unsigned)__bfloat16_as_ushort(l1) << 16);
    unsigned off = (unsigned)n * 128u + (unsigned)kp * 4u;
    unsigned sw = SW128(off);
    g_w2t_hi[sw >> 2] = hi;
    g_w2t_lo[sw >> 2] = lo;
}

// ============================================================
// node lin1
// ============================================================
__global__ __launch_bounds__(256) void node_lin1(
    const float* __restrict__ node_input,
    const float* __restrict__ w1s,
    const float* __restrict__ w1v)
{
    __shared__ float sWs[1024];
    __shared__ float sWv[1024];
    __shared__ float sRow[8][128];

    int t = threadIdx.x;
    for (int i = t; i < 1024; i += 256) {
        sWs[i] = w1s[i] * RSQRT32f;
        sWv[i] = w1v[i] * RSQRT32f;
    }
    int warp = t >> 5, lane = t & 31;
    int n = blockIdx.x * 8 + warp;

    const float4* rowp = reinterpret_cast<const float4*>(node_input + (size_t)n * 128);
    *reinterpret_cast<float4*>(&sRow[warp][lane * 4]) = rowp[lane];
    __syncthreads();

    const float* r = sRow[warp];
    float s = 0.f, v0 = 0.f, v1 = 0.f, v2 = 0.f;
#pragma unroll
    for (int u = 0; u < 32; u++) {
        float ws = sWs[u * 32 + lane];
        float wv = sWv[u * 32 + lane];
        s  += r[u] * ws;
        v0 += r[32 + u * 3 + 0] * wv;
        v1 += r[32 + u * 3 + 1] * wv;
        v2 += r[32 + u * 3 + 2] * wv;
    }
    float* o = g_feat + (size_t)n * 128;
    o[lane] = s;
    o[32 + lane * 3 + 0] = v0;
    o[32 + lane * 3 + 1] = v1;
    o[32 + lane * 3 + 2] = v2;
}

// ============================================================
// edge kernel: mma.sync bf16 3-term GEMM2 + messages + scatter
// 64 edges / 256-thread block
// ============================================================
__global__ __launch_bounds__(256) void edge_kernel(
    const int*   __restrict__ esrc,
    const int*   __restrict__ edst,
    const float* __restrict__ eattr,
    const float* __restrict__ escal,
    const float* __restrict__ fw1)
{
    extern __shared__ __align__(1024) char sm[];
    const unsigned smem_base = smem_u32(sm);
    const int t = threadIdx.x;
    const int eBase = blockIdx.x * 64;
    float* sW1 = reinterpret_cast<float*>(sm + SM_W1);

    // stage W1 (scaled) + pre-swizzled B hi/lo (linear copy)
    for (int i = t; i < 512; i += 256) sW1[i] = fw1[i] * RSQRT8f;
    {
        uint4* dh = reinterpret_cast<uint4*>(sm + SM_B_HI);
        uint4* dl = reinterpret_cast<uint4*>(sm + SM_B_LO);
        const uint4* shv = reinterpret_cast<const uint4*>(g_w2t_hi);
        const uint4* slv = reinterpret_cast<const uint4*>(g_w2t_lo);
        for (int i = t; i < 1024; i += 256) { dh[i] = shv[i]; dl[i] = slv[i]; }
    }
    __syncthreads();

    // ---- GEMM1: H[e,c] = silu(x @ W1)*SILUN -> bf16 hi/lo swizzled ----
    {
        const int e  = t & 63;
        const int c0 = (t >> 6) * 16;
        const float4* xp = reinterpret_cast<const float4*>(escal + (size_t)(eBase + e) * 8);
        float4 xa = xp[0], xb = xp[1];
        float x[8] = { xa.x, xa.y, xa.z, xa.w, xb.x, xb.y, xb.z, xb.w };
#pragma unroll
        for (int cc = 0; cc < 16; cc += 2) {
            float a0 = 0.f, a1 = 0.f;
#pragma unroll
            for (int k = 0; k < 8; k++) {
                a0 += x[k] * sW1[k * 64 + c0 + cc];
                a1 += x[k] * sW1[k * 64 + c0 + cc + 1];
            }
            float h0 = a0 * (1.f / (1.f + __expf(-a0))) * SILUNf;
            float h1 = a1 * (1.f / (1.f + __expf(-a1))) * SILUNf;
            __nv_bfloat16 b0 = __float2bfloat16(h0);
            __nv_bfloat16 b1 = __float2bfloat16(h1);
            __nv_bfloat16 r0 = __float2bfloat16(h0 - __bfloat162float(b0));
            __nv_bfloat16 r1 = __float2bfloat16(h1 - __bfloat162float(b1));
            unsigned hv = (unsigned)__bfloat16_as_ushort(b0) | ((unsigned)__bfloat16_as_ushort(b1) << 16);
            unsigned lv = (unsigned)__bfloat16_as_ushort(r0) | ((unsigned)__bfloat16_as_ushort(r1) << 16);
            unsigned off = (unsigned)e * 128u + (unsigned)(c0 + cc) * 2u;
            unsigned sw = SW128(off);
            *reinterpret_cast<unsigned*>(sm + SM_A_HI + sw) = hv;
            *reinterpret_cast<unsigned*>(sm + SM_A_LO + sw) = lv;
        }
    }
    __syncthreads();

    // ---- GEMM2 via mma.sync: D(64x128) = H(64x64) @ W2t^T, 3-term bf16 ----
    const int w = t >> 5, l = t & 31;
    const int mi = w & 3;       // m-tile (16 edges)
    const int nh = w >> 2;      // n-half (64 cols)

    float acc[8][4];
#pragma unroll
    for (int i = 0; i < 8; i++)
#pragma unroll
        for (int j = 0; j < 4; j++) acc[i][j] = 0.f;

    const int m_l  = (l & 7) + ((l >> 3) & 1) * 8;   // A lane row
    const int kqA  = ((l >> 4) & 1) * 8;             // A lane k-block
    const int nb_l = (l & 7) + ((l >> 4) & 1) * 8;   // B lane row (n)
    const int kqB  = ((l >> 3) & 1) * 8;             // B lane k-block

#pragma unroll
    for (int kt = 0; kt < 4; kt++) {
        unsigned offA = (unsigned)(mi * 16 + m_l) * 128u + (unsigned)(kt * 16 + kqA) * 2u;
        unsigned swA = SW128(offA);
        unsigned ah[4], al[4];
        ldm4(ah, smem_base + SM_A_HI + swA);
        ldm4(al, smem_base + SM_A_LO + swA);
#pragma unroll
        for (int p = 0; p < 4; p++) {
            unsigned offB = (unsigned)(nh * 64 + p * 16 + nb_l) * 128u
                          + (unsigned)(kt * 16 + kqB) * 2u;
            unsigned swB = SW128(offB);
            unsigned bh[4], bl[4];
            ldm4(bh, smem_base + SM_B_HI + swB);
            ldm4(bl, smem_base + SM_B_LO + swB);
            mma_bf16(acc[p * 2],     ah, bh);
            mma_bf16(acc[p * 2 + 1], ah, bh + 2);
            mma_bf16(acc[p * 2],     al, bh);
            mma_bf16(acc[p * 2 + 1], al, bh + 2);
            mma_bf16(acc[p * 2],     ah, bl);
            mma_bf16(acc[p * 2 + 1], ah, bl + 2);
        }
    }
    __syncthreads();   // everyone done reading A/B-hi before overlay

    // ---- spill D to shared: sWout[e][c], row = 128 f32 ----
    float* sWout = reinterpret_cast<float*>(sm);
    {
        const int r0 = mi * 16 + (l >> 2);
#pragma unroll
        for (int nt = 0; nt < 8; nt++) {
            const int c = nh * 64 + nt * 8 + (l & 3) * 2;
            *reinterpret_cast<float2*>(sWout + r0 * 128 + c)       = make_float2(acc[nt][0], acc[nt][1]);
            *reinterpret_cast<float2*>(sWout + (r0 + 8) * 128 + c) = make_float2(acc[nt][2], acc[nt][3]);
        }
    }
    __syncthreads();

    // ---- tensor-product messages + scatter-add (4 threads/edge) ----
    const int le = t >> 2;
    const int p  = t & 3;
    const int m0 = p * 8;
    const int e  = eBase + le;

    const int srcn = esrc[e];
    const int dstn = edst[e];
    float4 ea = *reinterpret_cast<const float4*>(eattr + (size_t)e * 4);
    const float es = ea.x, ev0 = ea.y, ev1 = ea.z, ev2 = ea.w;

    const float* feat = g_feat + (size_t)srcn * 128;
    float se[8];
    *reinterpret_cast<float4*>(&se[0]) = *reinterpret_cast<const float4*>(feat + m0);
    *reinterpret_cast<float4*>(&se[4]) = *reinterpret_cast<const float4*>(feat + m0 + 4);
    float ve[24];
#pragma unroll
    for (int q = 0; q < 6; q++)
        *reinterpret_cast<float4*>(&ve[q * 4]) =
            *reinterpret_cast<const float4*>(feat + 32 + m0 * 3 + q * 4);

    const float* Wp = sWout + le * 128 + m0;
    float w0[8], w1[8], w2[8], w3[8];
    *reinterpret_cast<float4*>(&w0[0]) = *reinterpret_cast<const float4*>(Wp + 0);
    *reinterpret_cast<float4*>(&w0[4]) = *reinterpret_cast<const float4*>(Wp + 4);
    *reinterpret_cast<float4*>(&w1[0]) = *reinterpret_cast<const float4*>(Wp + 32);
    *reinterpret_cast<float4*>(&w1[4]) = *reinterpret_cast<const float4*>(Wp + 36);
    *reinterpret_cast<float4*>(&w2[0]) = *reinterpret_cast<const float4*>(Wp + 64);
    *reinterpret_cast<float4*>(&w2[4]) = *reinterpret_cast<const float4*>(Wp + 68);
    *reinterpret_cast<float4*>(&w3[0]) = *reinterpret_cast<const float4*>(Wp + 96);
    *reinterpret_cast<float4*>(&w3[4]) = *reinterpret_cast<const float4*>(Wp + 100);

    float s0[8], s1[8], v0a[24], v1a[24];
#pragma unroll
    for (int j = 0; j < 8; j++) {
        float sej = se[j];
        s0[j] = w0[j] * sej * es;
        float dotp = ve[j * 3] * ev0 + ve[j * 3 + 1] * ev1 + ve[j * 3 + 2] * ev2;
        s1[j] = w3[j] * dotp * RSQRT3f;
        float a = w1[j] * sej;
        v0a[j * 3 + 0] = a * ev0;
        v0a[j * 3 + 1] = a * ev1;
        v0a[j * 3 + 2] = a * ev2;
        float b = w2[j] * es;
        v1a[j * 3 + 0] = b * ve[j * 3 + 0];
        v1a[j * 3 + 1] = b * ve[j * 3 + 1];
        v1a[j * 3 + 2] = b * ve[j * 3 + 2];
    }

    float* as = g_acc_s + (size_t)dstn * 64 + m0;
    red4(as,      s0[0], s0[1], s0[2], s0[3]);
    red4(as + 4,  s0[4], s0[5], s0[6], s0[7]);
    red4(as + 32, s1[0], s1[1], s1[2], s1[3]);
    red4(as + 36, s1[4], s1[5], s1[6], s1[7]);

    float* av = g_acc_v + (size_t)dstn * 192 + m0 * 3;
#pragma unroll
    for (int q = 0; q < 6; q++)
        red4(av + q * 4, v0a[q * 4], v0a[q * 4 + 1], v0a[q * 4 + 2], v0a[q * 4 + 3]);
#pragma unroll
    for (int q = 0; q < 6; q++)
        red4(av + 96 + q * 4, v1a[q * 4], v1a[q * 4 + 1], v1a[q * 4 + 2], v1a[q * 4 + 3]);
}

// ============================================================
// node lin2 + output
// ============================================================
__global__ __launch_bounds__(256) void node_lin2(
    const float* __restrict__ w2s,
    const float* __restrict__ w2v,
    float* __restrict__ out)
{
    __shared__ float sWs[2048];
    __shared__ float sWv[2048];
    __shared__ float sRow[8][256];

    int t = threadIdx.x;
    for (int i = t; i < 2048; i += 256) {
        sWs[i] = w2s[i] * SCALE2f;
        sWv[i] = w2v[i] * SCALE2f;
    }
    int warp = t >> 5, lane = t & 31;
    int n = blockIdx.x * 8 + warp;

    const float4* ap = reinterpret_cast<const float4*>(g_acc_s + (size_t)n * 64);
    const float4* vp = reinterpret_cast<const float4*>(g_acc_v + (size_t)n * 192);
    if (lane < 16)
        *reinterpret_cast<float4*>(&sRow[warp][lane * 4]) = ap[lane];
    *reinterpret_cast<float4*>(&sRow[warp][64 + lane * 4]) = vp[lane];
    if (lane < 16)
        *reinterpret_cast<float4*>(&sRow[warp][64 + 128 + lane * 4]) = vp[32 + lane];
    __syncthreads();

    const float* r = sRow[warp];
    float s = 0.f, v0 = 0.f, v1 = 0.f, v2 = 0.f;
#pragma unroll
    for (int u = 0; u < 64; u++) {
        s += r[u] * sWs[u * 32 + lane];
        float wv = sWv[u * 32 + lane];
        v0 += r[64 + u * 3 + 0] * wv;
        v1 += r[64 + u * 3 + 1] * wv;
        v2 += r[64 + u * 3 + 2] * wv;
    }
    float* o = out + (size_t)n * 128;
    o[lane] = s;
    o[32 + lane * 3 + 0] = v0;
    o[32 + lane * 3 + 1] = v1;
    o[32 + lane * 3 + 2] = v2;
}

// ============================================================
// launch
// ============================================================
extern "C" void kernel_launch(void* const* d_in, const int* in_sizes, int n_in,
                              void* d_out, int out_size)
{
    const float* node_input = (const float*)d_in[0];
    const int*   esrc  = (const int*)d_in[2];
    const int*   edst  = (const int*)d_in[3];
    const float* eattr = (const float*)d_in[4];
    const float* escal = (const float*)d_in[5];
    const float* w1s   = (const float*)d_in[6];
    const float* w1v   = (const float*)d_in[7];
    const float* fw1   = (const float*)d_in[8];
    const float* fw2   = (const float*)d_in[9];
    const float* w2s   = (const float*)d_in[10];
    const float* w2v   = (const float*)d_in[11];
    float* out = (float*)d_out;

    zero_acc<<<2048, 256>>>();
    prep_w2t<<<16, 256>>>(fw2);
    node_lin1<<<NN / 8, 256>>>(node_input, w1s, w1v);

    cudaFuncSetAttribute(edge_kernel, cudaFuncAttributeMaxDynamicSharedMemorySize, SM_TOTAL);
    edge_kernel<<<NE / 64, 256, SM_TOTAL>>>(esrc, edst, eattr, escal, fw1);

    node_lin2<<<NN / 8, 256>>>(w2s, w2v, out);
}

// round 15
// speedup vs baseline: 1.3137x; 1.0145x over previous
#include <cuda_runtime.h>
#include <cuda_bf16.h>
#include <math.h>

#define NN 40000
#define NE 640000

#define RSQRT32f 0.1767766952966368811f
#define RSQRT8f  0.3535533905932737622f
#define SILUNf   1.6791767923989418f
#define RSQRT3f  0.5773502691896257645f
#define SCALE2f  0.03125f

// ---- device scratch ----
__device__ float g_feat [NN * 128];
__device__ float g_acc_s[NN * 64];
__device__ float g_acc_v[NN * 192];
__device__ __align__(16) unsigned g_w2t_hi[4096];  // [128n x 64k] bf16 pairs, SW128-swizzled
__device__ __align__(16) unsigned g_w2t_lo[4096];

__device__ __forceinline__ void red4(float* p, float a, float b, float c, float d) {
    asm volatile("red.global.add.v4.f32 [%0], {%1,%2,%3,%4};"
                 :: "l"(p), "f"(a), "f"(b), "f"(c), "f"(d) : "memory");
}
__device__ __forceinline__ unsigned smem_u32(const void* p) {
    unsigned a;
    asm("{ .reg .u64 t; cvta.to.shared.u64 t, %1; cvt.u32.u64 %0, t; }" : "=r"(a) : "l"(p));
    return a;
}
__device__ __forceinline__ void ldm4(unsigned* r, unsigned addr) {
    asm volatile("ldmatrix.sync.aligned.m8n8.x4.shared.b16 {%0,%1,%2,%3}, [%4];"
                 : "=r"(r[0]), "=r"(r[1]), "=r"(r[2]), "=r"(r[3]) : "r"(addr));
}
__device__ __forceinline__ void mma_bf16(float* d, const unsigned* a, const unsigned* b) {
    asm volatile("mma.sync.aligned.m16n8k16.row.col.f32.bf16.bf16.f32 "
                 "{%0,%1,%2,%3}, {%4,%5,%6,%7}, {%8,%9}, {%0,%1,%2,%3};"
                 : "+f"(d[0]), "+f"(d[1]), "+f"(d[2]), "+f"(d[3])
                 : "r"(a[0]), "r"(a[1]), "r"(a[2]), "r"(a[3]), "r"(b[0]), "r"(b[1]));
}

#define SW128(off) ((off) ^ (((off) >> 3) & 0x70))

// SMEM layout (bytes); sWout (64x128 f32 = 32768B) overlays [0,32768) after MMA.
#define SM_A_HI 0
#define SM_A_LO 8192
#define SM_B_HI 16384
#define SM_B_LO 32768
#define SM_W1   49152
#define SM_TOTAL 51200

// ============================================================
// zero accumulators
// ============================================================
__global__ void zero_acc() {
    const float4 z = make_float4(0.f, 0.f, 0.f, 0.f);
    float4* a = reinterpret_cast<float4*>(g_acc_s);
    float4* b = reinterpret_cast<float4*>(g_acc_v);
    int idx = blockIdx.x * blockDim.x + threadIdx.x;
    int stride = gridDim.x * blockDim.x;
    for (int i = idx; i < NN * 64 / 4;  i += stride) a[i] = z;
    for (int i = idx; i < NN * 192 / 4; i += stride) b[i] = z;
}

// ============================================================
// prep: W2^T (scaled 1/8) -> bf16 hi/lo, [n][k] rows, SW128 image
// ============================================================
__global__ void prep_w2t(const float* __restrict__ fw2) {
    int idx = blockIdx.x * blockDim.x + threadIdx.x;   // 0..4095
    int n  = idx >> 5;
    int kp = idx & 31;
    int k  = kp * 2;
    float v0 = fw2[(size_t)k * 128 + n] * 0.125f;
    float v1 = fw2[(size_t)(k + 1) * 128 + n] * 0.125f;
    __nv_bfloat16 h0 = __float2bfloat16(v0);
    __nv_bfloat16 h1 = __float2bfloat16(v1);
    __nv_bfloat16 l0 = __float2bfloat16(v0 - __bfloat162float(h0));
    __nv_bfloat16 l1 = __float2bfloat16(v1 - __bfloat162float(h1));
    unsigned hi = (unsigned)__bfloat16_as_ushort(h0) | ((unsigned)__bfloat16_as_ushort(h1) << 16);
    unsigned lo = (unsigned)__bfloat16_as_ushort(l0) | ((unsigned)__bfloat16_as_ushort(l1) << 16);
    unsigned off = (unsigned)n * 128u + (unsigned)kp * 4u;
    unsigned sw = SW128(off);
    g_w2t_hi[sw >> 2] = hi;
    g_w2t_lo[sw >> 2] = lo;
}

// ============================================================
// node lin1 — transposed weights, float4 LDS
// sWT row stride 36 floats (aligned, phase-conflict-free)
// ============================================================
__global__ __launch_bounds__(256) void node_lin1(
    const float* __restrict__ node_input,
    const float* __restrict__ w1s,
    const float* __restrict__ w1v)
{
    __shared__ float sWsT[32 * 36];
    __shared__ float sWvT[32 * 36];
    __shared__ float sRow[8][128];

    int t = threadIdx.x;
    for (int i = t; i < 1024; i += 256) {
        int u = i >> 5, c = i & 31;
        sWsT[c * 36 + u] = w1s[i] * RSQRT32f;
        sWvT[c * 36 + u] = w1v[i] * RSQRT32f;
    }
    int warp = t >> 5, lane = t & 31;
    int n = blockIdx.x * 8 + warp;

    const float4* rowp = reinterpret_cast<const float4*>(node_input + (size_t)n * 128);
    *reinterpret_cast<float4*>(&sRow[warp][lane * 4]) = rowp[lane];
    __syncthreads();

    const float* r = sRow[warp];
    const float* ws = sWsT + lane * 36;
    const float* wv = sWvT + lane * 36;
    float s = 0.f, v0 = 0.f, v1 = 0.f, v2 = 0.f;
#pragma unroll
    for (int u4 = 0; u4 < 32; u4 += 4) {
        float4 wsq = *reinterpret_cast<const float4*>(ws + u4);
        float4 wvq = *reinterpret_cast<const float4*>(wv + u4);
        float4 rs  = *reinterpret_cast<const float4*>(r + u4);
        float4 ra  = *reinterpret_cast<const float4*>(r + 32 + u4 * 3);
        float4 rb  = *reinterpret_cast<const float4*>(r + 32 + u4 * 3 + 4);
        float4 rc  = *reinterpret_cast<const float4*>(r + 32 + u4 * 3 + 8);
        s += rs.x * wsq.x + rs.y * wsq.y + rs.z * wsq.z + rs.w * wsq.w;
        v0 += ra.x * wvq.x; v1 += ra.y * wvq.x; v2 += ra.z * wvq.x;
        v0 += ra.w * wvq.y; v1 += rb.x * wvq.y; v2 += rb.y * wvq.y;
        v0 += rb.z * wvq.z; v1 += rb.w * wvq.z; v2 += rc.x * wvq.z;
        v0 += rc.y * wvq.w; v1 += rc.z * wvq.w; v2 += rc.w * wvq.w;
    }
    float* o = g_feat + (size_t)n * 128;
    o[lane] = s;
    o[32 + lane * 3 + 0] = v0;
    o[32 + lane * 3 + 1] = v1;
    o[32 + lane * 3 + 2] = v2;
}

// ============================================================
// edge kernel: mma.sync bf16 3-term GEMM2 + messages + scatter
// 64 edges / 256-thread block, 4 CTAs/SM
// ============================================================
__global__ __launch_bounds__(256, 4) void edge_kernel(
    const int*   __restrict__ esrc,
    const int*   __restrict__ edst,
    const float* __restrict__ eattr,
    const float* __restrict__ escal,
    const float* __restrict__ fw1)
{
    extern __shared__ __align__(1024) char sm[];
    const unsigned smem_base = smem_u32(sm);
    const int t = threadIdx.x;
    const int eBase = blockIdx.x * 64;
    float* sW1 = reinterpret_cast<float*>(sm + SM_W1);

    // stage W1 (scaled) + pre-swizzled B hi/lo (linear copy)
    for (int i = t; i < 512; i += 256) sW1[i] = fw1[i] * RSQRT8f;
    {
        uint4* dh = reinterpret_cast<uint4*>(sm + SM_B_HI);
        uint4* dl = reinterpret_cast<uint4*>(sm + SM_B_LO);
        const uint4* shv = reinterpret_cast<const uint4*>(g_w2t_hi);
        const uint4* slv = reinterpret_cast<const uint4*>(g_w2t_lo);
        for (int i = t; i < 1024; i += 256) { dh[i] = shv[i]; dl[i] = slv[i]; }
    }
    __syncthreads();

    // ---- GEMM1: H[e,c] = silu(x @ W1)*SILUN -> bf16 hi/lo swizzled ----
    {
        const int e  = t & 63;
        const int c0 = (t >> 6) * 16;
        const float4* xp = reinterpret_cast<const float4*>(escal + (size_t)(eBase + e) * 8);
        float4 xa = xp[0], xb = xp[1];
        float x[8] = { xa.x, xa.y, xa.z, xa.w, xb.x, xb.y, xb.z, xb.w };
#pragma unroll
        for (int cc = 0; cc < 16; cc += 2) {
            float a0 = 0.f, a1 = 0.f;
#pragma unroll
            for (int k = 0; k < 8; k++) {
                a0 += x[k] * sW1[k * 64 + c0 + cc];
                a1 += x[k] * sW1[k * 64 + c0 + cc + 1];
            }
            float h0 = a0 * (1.f / (1.f + __expf(-a0))) * SILUNf;
            float h1 = a1 * (1.f / (1.f + __expf(-a1))) * SILUNf;
            __nv_bfloat16 b0 = __float2bfloat16(h0);
            __nv_bfloat16 b1 = __float2bfloat16(h1);
            __nv_bfloat16 r0 = __float2bfloat16(h0 - __bfloat162float(b0));
            __nv_bfloat16 r1 = __float2bfloat16(h1 - __bfloat162float(b1));
            unsigned hv = (unsigned)__bfloat16_as_ushort(b0) | ((unsigned)__bfloat16_as_ushort(b1) << 16);
            unsigned lv = (unsigned)__bfloat16_as_ushort(r0) | ((unsigned)__bfloat16_as_ushort(r1) << 16);
            unsigned off = (unsigned)e * 128u + (unsigned)(c0 + cc) * 2u;
            unsigned sw = SW128(off);
            *reinterpret_cast<unsigned*>(sm + SM_A_HI + sw) = hv;
            *reinterpret_cast<unsigned*>(sm + SM_A_LO + sw) = lv;
        }
    }
    __syncthreads();

    // ---- GEMM2 via mma.sync: D(64x128) = H(64x64) @ W2t^T, 3-term bf16 ----
    const int w = t >> 5, l = t & 31;
    const int mi = w & 3;       // m-tile (16 edges)
    const int nh = w >> 2;      // n-half (64 cols)

    float acc[8][4];
#pragma unroll
    for (int i = 0; i < 8; i++)
#pragma unroll
        for (int j = 0; j < 4; j++) acc[i][j] = 0.f;

    const int m_l  = (l & 7) + ((l >> 3) & 1) * 8;
    const int kqA  = ((l >> 4) & 1) * 8;
    const int nb_l = (l & 7) + ((l >> 4) & 1) * 8;
    const int kqB  = ((l >> 3) & 1) * 8;

#pragma unroll
    for (int kt = 0; kt < 4; kt++) {
        unsigned offA = (unsigned)(mi * 16 + m_l) * 128u + (unsigned)(kt * 16 + kqA) * 2u;
        unsigned swA = SW128(offA);
        unsigned ah[4], al[4];
        ldm4(ah, smem_base + SM_A_HI + swA);
        ldm4(al, smem_base + SM_A_LO + swA);
#pragma unroll
        for (int p = 0; p < 4; p++) {
            unsigned offB = (unsigned)(nh * 64 + p * 16 + nb_l) * 128u
                          + (unsigned)(kt * 16 + kqB) * 2u;
            unsigned swB = SW128(offB);
            unsigned bh[4], bl[4];
            ldm4(bh, smem_base + SM_B_HI + swB);
            ldm4(bl, smem_base + SM_B_LO + swB);
            mma_bf16(acc[p * 2],     ah, bh);
            mma_bf16(acc[p * 2 + 1], ah, bh + 2);
            mma_bf16(acc[p * 2],     al, bh);
            mma_bf16(acc[p * 2 + 1], al, bh + 2);
            mma_bf16(acc[p * 2],     ah, bl);
            mma_bf16(acc[p * 2 + 1], ah, bl + 2);
        }
    }
    __syncthreads();   // everyone done reading A/B-hi before overlay

    // ---- spill D to shared: sWout[e][c] ----
    float* sWout = reinterpret_cast<float*>(sm);
    {
        const int r0 = mi * 16 + (l >> 2);
#pragma unroll
        for (int nt = 0; nt < 8; nt++) {
            const int c = nh * 64 + nt * 8 + (l & 3) * 2;
            *reinterpret_cast<float2*>(sWout + r0 * 128 + c)       = make_float2(acc[nt][0], acc[nt][1]);
            *reinterpret_cast<float2*>(sWout + (r0 + 8) * 128 + c) = make_float2(acc[nt][2], acc[nt][3]);
        }
    }
    __syncthreads();

    // ---- tensor-product messages + scatter-add (4 threads/edge, 2 passes) ----
    const int le = t >> 2;
    const int p  = t & 3;
    const int e  = eBase + le;

    const int srcn = esrc[e];
    const int dstn = edst[e];
    float4 ea = *reinterpret_cast<const float4*>(eattr + (size_t)e * 4);
    const float es = ea.x, ev0 = ea.y, ev1 = ea.z, ev2 = ea.w;

    const float* feat = g_feat + (size_t)srcn * 128;
    const float* Wrow = sWout + le * 128;
    float* as = g_acc_s + (size_t)dstn * 64;
    float* av = g_acc_v + (size_t)dstn * 192;

#pragma unroll
    for (int h = 0; h < 2; h++) {
        const int m0 = p * 8 + h * 4;
        float4 se = *reinterpret_cast<const float4*>(feat + m0);
        float4 w0 = *reinterpret_cast<const float4*>(Wrow + m0);
        float4 w1 = *reinterpret_cast<const float4*>(Wrow + 32 + m0);
        float4 w2 = *reinterpret_cast<const float4*>(Wrow + 64 + m0);
        float4 w3 = *reinterpret_cast<const float4*>(Wrow + 96 + m0);
        float ve[12];
        *reinterpret_cast<float4*>(ve + 0) = *reinterpret_cast<const float4*>(feat + 32 + m0 * 3);
        *reinterpret_cast<float4*>(ve + 4) = *reinterpret_cast<const float4*>(feat + 32 + m0 * 3 + 4);
        *reinterpret_cast<float4*>(ve + 8) = *reinterpret_cast<const float4*>(feat + 32 + m0 * 3 + 8);

        red4(as + m0, w0.x * se.x * es, w0.y * se.y * es, w0.z * se.z * es, w0.w * se.w * es);

        float d0 = ve[0] * ev0 + ve[1]  * ev1 + ve[2]  * ev2;
        float d1 = ve[3] * ev0 + ve[4]  * ev1 + ve[5]  * ev2;
        float d2 = ve[6] * ev0 + ve[7]  * ev1 + ve[8]  * ev2;
        float d3 = ve[9] * ev0 + ve[10] * ev1 + ve[11] * ev2;
        red4(as + 32 + m0, w3.x * d0 * RSQRT3f, w3.y * d1 * RSQRT3f,
                           w3.z * d2 * RSQRT3f, w3.w * d3 * RSQRT3f);

        float a0 = w1.x * se.x, a1 = w1.y * se.y, a2 = w1.z * se.z, a3 = w1.w * se.w;
        float* pv = av + m0 * 3;
        red4(pv + 0, a0 * ev0, a0 * ev1, a0 * ev2, a1 * ev0);
        red4(pv + 4, a1 * ev1, a1 * ev2, a2 * ev0, a2 * ev1);
        red4(pv + 8, a2 * ev2, a3 * ev0, a3 * ev1, a3 * ev2);

        float b0 = w2.x * es, b1 = w2.y * es, b2 = w2.z * es, b3 = w2.w * es;
        float* qv = av + 96 + m0 * 3;
        red4(qv + 0, b0 * ve[0], b0 * ve[1], b0 * ve[2],  b1 * ve[3]);
        red4(qv + 4, b1 * ve[4], b1 * ve[5], b2 * ve[6],  b2 * ve[7]);
        red4(qv + 8, b2 * ve[8], b3 * ve[9], b3 * ve[10], b3 * ve[11]);
    }
}

// ============================================================
// node lin2 — transposed weights, float4 LDS
// ============================================================
__global__ __launch_bounds__(256) void node_lin2(
    const float* __restrict__ w2s,
    const float* __restrict__ w2v,
    float* __restrict__ out)
{
    __shared__ float sWsT[32 * 68];
    __shared__ float sWvT[32 * 68];
    __shared__ float sRow[8][256];

    int t = threadIdx.x;
    for (int i = t; i < 2048; i += 256) {
        int u = i >> 5, c = i & 31;
        sWsT[c * 68 + u] = w2s[i] * SCALE2f;
        sWvT[c * 68 + u] = w2v[i] * SCALE2f;
    }
    int warp = t >> 5, lane = t & 31;
    int n = blockIdx.x * 8 + warp;

    const float4* ap = reinterpret_cast<const float4*>(g_acc_s + (size_t)n * 64);
    const float4* vp = reinterpret_cast<const float4*>(g_acc_v + (size_t)n * 192);
    if (lane < 16)
        *reinterpret_cast<float4*>(&sRow[warp][lane * 4]) = ap[lane];
    *reinterpret_cast<float4*>(&sRow[warp][64 + lane * 4]) = vp[lane];
    if (lane < 16)
        *reinterpret_cast<float4*>(&sRow[warp][64 + 128 + lane * 4]) = vp[32 + lane];
    __syncthreads();

    const float* r = sRow[warp];
    const float* ws = sWsT + lane * 68;
    const float* wv = sWvT + lane * 68;
    float s = 0.f, v0 = 0.f, v1 = 0.f, v2 = 0.f;
#pragma unroll
    for (int u4 = 0; u4 < 64; u4 += 4) {
        float4 wsq = *reinterpret_cast<const float4*>(ws + u4);
        float4 wvq = *reinterpret_cast<const float4*>(wv + u4);
        float4 rs  = *reinterpret_cast<const float4*>(r + u4);
        float4 ra  = *reinterpret_cast<const float4*>(r + 64 + u4 * 3);
        float4 rb  = *reinterpret_cast<const float4*>(r + 64 + u4 * 3 + 4);
        float4 rc  = *reinterpret_cast<const float4*>(r + 64 + u4 * 3 + 8);
        s += rs.x * wsq.x + rs.y * wsq.y + rs.z * wsq.z + rs.w * wsq.w;
        v0 += ra.x * wvq.x; v1 += ra.y * wvq.x; v2 += ra.z * wvq.x;
        v0 += ra.w * wvq.y; v1 += rb.x * wvq.y; v2 += rb.y * wvq.y;
        v0 += rb.z * wvq.z; v1 += rb.w * wvq.z; v2 += rc.x * wvq.z;
        v0 += rc.y * wvq.w; v1 += rc.z * wvq.w; v2 += rc.w * wvq.w;
    }
    float* o = out + (size_t)n * 128;
    o[lane] = s;
    o[32 + lane * 3 + 0] = v0;
    o[32 + lane * 3 + 1] = v1;
    o[32 + lane * 3 + 2] = v2;
}

// ============================================================
// launch
// ============================================================
extern "C" void kernel_launch(void* const* d_in, const int* in_sizes, int n_in,
                              void* d_out, int out_size)
{
    const float* node_input = (const float*)d_in[0];
    const int*   esrc  = (const int*)d_in[2];
    const int*   edst  = (const int*)d_in[3];
    const float* eattr = (const float*)d_in[4];
    const float* escal = (const float*)d_in[5];
    const float* w1s   = (const float*)d_in[6];
    const float* w1v   = (const float*)d_in[7];
    const float* fw1   = (const float*)d_in[8];
    const float* fw2   = (const float*)d_in[9];
    const float* w2s   = (const float*)d_in[10];
    const float* w2v   = (const float*)d_in[11];
    float* out = (float*)d_out;

    zero_acc<<<2048, 256>>>();
    prep_w2t<<<16, 256>>>(fw2);
    node_lin1<<<NN / 8, 256>>>(node_input, w1s, w1v);

    cudaFuncSetAttribute(edge_kernel, cudaFuncAttributeMaxDynamicSharedMemorySize, SM_TOTAL);
    edge_kernel<<<NE / 64, 256, SM_TOTAL>>>(esrc, edst, eattr, escal, fw1);

    node_lin2<<<NN / 8, 256>>>(w2s, w2v, out);
}

// round 17
// speedup vs baseline: 1.3648x; 1.0389x over previous
#include <cuda_runtime.h>
#include <cuda_bf16.h>
#include <math.h>

#define NN 40000
#define NE 640000

#define RSQRT32f 0.1767766952966368811f
#define RSQRT8f  0.3535533905932737622f
#define SILUNf   1.6791767923989418f
#define RSQRT3f  0.5773502691896257645f
#define SCALE2f  0.03125f

// ---- device scratch ----
__device__ float g_feat [NN * 128];
__device__ float g_acc_s[NN * 64];
__device__ float g_acc_v[NN * 192];
__device__ __align__(16) unsigned g_w2t_hi[4096];  // [128n x 64k] bf16 pairs, SW128-swizzled
__device__ __align__(16) unsigned g_w2t_lo[4096];

__device__ __forceinline__ void red4(float* p, float a, float b, float c, float d) {
    asm volatile("red.global.add.v4.f32 [%0], {%1,%2,%3,%4};"
                 :: "l"(p), "f"(a), "f"(b), "f"(c), "f"(d) : "memory");
}
__device__ __forceinline__ unsigned smem_u32(const void* p) {
    unsigned a;
    asm("{ .reg .u64 t; cvta.to.shared.u64 t, %1; cvt.u32.u64 %0, t; }" : "=r"(a) : "l"(p));
    return a;
}
__device__ __forceinline__ void ldm4(unsigned* r, unsigned addr) {
    asm volatile("ldmatrix.sync.aligned.m8n8.x4.shared.b16 {%0,%1,%2,%3}, [%4];"
                 : "=r"(r[0]), "=r"(r[1]), "=r"(r[2]), "=r"(r[3]) : "r"(addr));
}
__device__ __forceinline__ void mma_bf16(float* d, const unsigned* a, const unsigned* b) {
    asm volatile("mma.sync.aligned.m16n8k16.row.col.f32.bf16.bf16.f32 "
                 "{%0,%1,%2,%3}, {%4,%5,%6,%7}, {%8,%9}, {%0,%1,%2,%3};"
                 : "+f"(d[0]), "+f"(d[1]), "+f"(d[2]), "+f"(d[3])
                 : "r"(a[0]), "r"(a[1]), "r"(a[2]), "r"(a[3]), "r"(b[0]), "r"(b[1]));
}

#define SW128(off) ((off) ^ (((off) >> 3) & 0x70))

// SMEM layout (bytes).
// sWout (64 rows x 132 f32 stride = 33792B) overlays [0, 33792) after GEMM2.
#define SM_A_HI 0
#define SM_A_LO 8192
#define SM_B_HI 16384
#define SM_B_LO 32768
#define SM_W1T  49152          // 64 rows x 12 floats = 3072B
#define SM_TOTAL 52224
#define WOUT_STRIDE 132

// ============================================================
// zero accumulators
// ============================================================
__global__ void zero_acc() {
    const float4 z = make_float4(0.f, 0.f, 0.f, 0.f);
    float4* a = reinterpret_cast<float4*>(g_acc_s);
    float4* b = reinterpret_cast<float4*>(g_acc_v);
    int idx = blockIdx.x * blockDim.x + threadIdx.x;
    int stride = gridDim.x * blockDim.x;
    for (int i = idx; i < NN * 64 / 4;  i += stride) a[i] = z;
    for (int i = idx; i < NN * 192 / 4; i += stride) b[i] = z;
}

// ============================================================
// prep: W2^T (scaled 1/8) -> bf16 hi/lo, [n][k] rows, SW128 image
// ============================================================
__global__ void prep_w2t(const float* __restrict__ fw2) {
    int idx = blockIdx.x * blockDim.x + threadIdx.x;   // 0..4095
    int n  = idx >> 5;
    int kp = idx & 31;
    int k  = kp * 2;
    float v0 = fw2[(size_t)k * 128 + n] * 0.125f;
    float v1 = fw2[(size_t)(k + 1) * 128 + n] * 0.125f;
    __nv_bfloat16 h0 = __float2bfloat16(v0);
    __nv_bfloat16 h1 = __float2bfloat16(v1);
    __nv_bfloat16 l0 = __float2bfloat16(v0 - __bfloat162float(h0));
    __nv_bfloat16 l1 = __float2bfloat16(v1 - __bfloat162float(h1));
    unsigned hi = (unsigned)__bfloat16_as_ushort(h0) | ((unsigned)__bfloat16_as_ushort(h1) << 16);
    unsigned lo = (unsigned)__bfloat16_as_ushort(l0) | ((unsigned)__bfloat16_as_ushort(l1) << 16);
    unsigned off = (unsigned)n * 128u + (unsigned)kp * 4u;
    unsigned sw = SW128(off);
    g_w2t_hi[sw >> 2] = hi;
    g_w2t_lo[sw >> 2] = lo;
}

// ============================================================
// node lin1 — transposed weights, float4 LDS
// ============================================================
__global__ __launch_bounds__(256) void node_lin1(
    const float* __restrict__ node_input,
    const float* __restrict__ w1s,
    const float* __restrict__ w1v)
{
    __shared__ float sWsT[32 * 36];
    __shared__ float sWvT[32 * 36];
    __shared__ float sRow[8][128];

    int t = threadIdx.x;
    for (int i = t; i < 1024; i += 256) {
        int u = i >> 5, c = i & 31;
        sWsT[c * 36 + u] = w1s[i] * RSQRT32f;
        sWvT[c * 36 + u] = w1v[i] * RSQRT32f;
    }
    int warp = t >> 5, lane = t & 31;
    int n = blockIdx.x * 8 + warp;

    const float4* rowp = reinterpret_cast<const float4*>(node_input + (size_t)n * 128);
    *reinterpret_cast<float4*>(&sRow[warp][lane * 4]) = rowp[lane];
    __syncthreads();

    const float* r = sRow[warp];
    const float* ws = sWsT + lane * 36;
    const float* wv = sWvT + lane * 36;
    float s = 0.f, v0 = 0.f, v1 = 0.f, v2 = 0.f;
#pragma unroll
    for (int u4 = 0; u4 < 32; u4 += 4) {
        float4 wsq = *reinterpret_cast<const float4*>(ws + u4);
        float4 wvq = *reinterpret_cast<const float4*>(wv + u4);
        float4 rs  = *reinterpret_cast<const float4*>(r + u4);
        float4 ra  = *reinterpret_cast<const float4*>(r + 32 + u4 * 3);
        float4 rb  = *reinterpret_cast<const float4*>(r + 32 + u4 * 3 + 4);
        float4 rc  = *reinterpret_cast<const float4*>(r + 32 + u4 * 3 + 8);
        s += rs.x * wsq.x + rs.y * wsq.y + rs.z * wsq.z + rs.w * wsq.w;
        v0 += ra.x * wvq.x; v1 += ra.y * wvq.x; v2 += ra.z * wvq.x;
        v0 += ra.w * wvq.y; v1 += rb.x * wvq.y; v2 += rb.y * wvq.y;
        v0 += rb.z * wvq.z; v1 += rb.w * wvq.z; v2 += rc.x * wvq.z;
        v0 += rc.y * wvq.w; v1 += rc.z * wvq.w; v2 += rc.w * wvq.w;
    }
    float* o = g_feat + (size_t)n * 128;
    o[lane] = s;
    o[32 + lane * 3 + 0] = v0;
    o[32 + lane * 3 + 1] = v1;
    o[32 + lane * 3 + 2] = v2;
}

// ============================================================
// edge kernel: mma.sync bf16 3-term GEMM2 + messages + scatter
// 64 edges / 256-thread block, 4 CTAs/SM
// ============================================================
__global__ __launch_bounds__(256, 4) void edge_kernel(
    const int*   __restrict__ esrc,
    const int*   __restrict__ edst,
    const float* __restrict__ eattr,
    const float* __restrict__ escal,
    const float* __restrict__ fw1)
{
    extern __shared__ __align__(1024) char sm[];
    const unsigned smem_base = smem_u32(sm);
    const int t = threadIdx.x;
    const int eBase = blockIdx.x * 64;
    float* sW1T = reinterpret_cast<float*>(sm + SM_W1T);

    // stage W1 transposed (stride 12) + pre-swizzled B hi/lo (linear copy)
    for (int i = t; i < 512; i += 256) {
        int k = i >> 6, c = i & 63;
        sW1T[c * 12 + k] = fw1[i] * RSQRT8f;
    }
    {
        uint4* dh = reinterpret_cast<uint4*>(sm + SM_B_HI);
        uint4* dl = reinterpret_cast<uint4*>(sm + SM_B_LO);
        const uint4* shv = reinterpret_cast<const uint4*>(g_w2t_hi);
        const uint4* slv = reinterpret_cast<const uint4*>(g_w2t_lo);
        for (int i = t; i < 1024; i += 256) { dh[i] = shv[i]; dl[i] = slv[i]; }
    }
    __syncthreads();

    // ---- GEMM1: H[e,c] = silu(x @ W1)*SILUN -> bf16 hi/lo swizzled ----
    // mapping: e = t>>2 (8 e/warp), cq = t&3; c-pairs strided 8 -> bank-disjoint
    {
        const int e  = t >> 2;
        const int cq = t & 3;
        const float4* xp = reinterpret_cast<const float4*>(escal + (size_t)(eBase + e) * 8);
        float4 xa = xp[0], xb = xp[1];
#pragma unroll
        for (int j = 0; j < 8; j++) {
            const int c = cq * 2 + j * 8;
            float4 wa0 = *reinterpret_cast<const float4*>(sW1T + c * 12);
            float4 wb0 = *reinterpret_cast<const float4*>(sW1T + c * 12 + 4);
            float4 wa1 = *reinterpret_cast<const float4*>(sW1T + (c + 1) * 12);
            float4 wb1 = *reinterpret_cast<const float4*>(sW1T + (c + 1) * 12 + 4);
            float a0 = xa.x*wa0.x + xa.y*wa0.y + xa.z*wa0.z + xa.w*wa0.w
                     + xb.x*wb0.x + xb.y*wb0.y + xb.z*wb0.z + xb.w*wb0.w;
            float a1 = xa.x*wa1.x + xa.y*wa1.y + xa.z*wa1.z + xa.w*wa1.w
                     + xb.x*wb1.x + xb.y*wb1.y + xb.z*wb1.z + xb.w*wb1.w;
            float h0 = a0 * (1.f / (1.f + __expf(-a0))) * SILUNf;
            float h1 = a1 * (1.f / (1.f + __expf(-a1))) * SILUNf;
            __nv_bfloat16 b0 = __float2bfloat16(h0);
            __nv_bfloat16 b1 = __float2bfloat16(h1);
            __nv_bfloat16 r0 = __float2bfloat16(h0 - __bfloat162float(b0));
            __nv_bfloat16 r1 = __float2bfloat16(h1 - __bfloat162float(b1));
            unsigned hv = (unsigned)__bfloat16_as_ushort(b0) | ((unsigned)__bfloat16_as_ushort(b1) << 16);
            unsigned lv = (unsigned)__bfloat16_as_ushort(r0) | ((unsigned)__bfloat16_as_ushort(r1) << 16);
            unsigned off = (unsigned)e * 128u + (unsigned)c * 2u;
            unsigned sw = SW128(off);
            *reinterpret_cast<unsigned*>(sm + SM_A_HI + sw) = hv;
            *reinterpret_cast<unsigned*>(sm + SM_A_LO + sw) = lv;
        }
    }
    __syncthreads();

    // ---- GEMM2 via mma.sync: D(64x128) = H(64x64) @ W2t^T, 3-term bf16 ----
    const int w = t >> 5, l = t & 31;
    const int mi = w & 3;       // m-tile (16 edges)
    const int nh = w >> 2;      // n-half (64 cols)

    float acc[8][4];
#pragma unroll
    for (int i = 0; i < 8; i++)
#pragma unroll
        for (int j = 0; j < 4; j++) acc[i][j] = 0.f;

    const int m_l  = (l & 7) + ((l >> 3) & 1) * 8;
    const int kqA  = ((l >> 4) & 1) * 8;
    const int nb_l = (l & 7) + ((l >> 4) & 1) * 8;
    const int kqB  = ((l >> 3) & 1) * 8;

#pragma unroll
    for (int kt = 0; kt < 4; kt++) {
        unsigned offA = (unsigned)(mi * 16 + m_l) * 128u + (unsigned)(kt * 16 + kqA) * 2u;
        unsigned swA = SW128(offA);
        unsigned ah[4], al[4];
        ldm4(ah, smem_base + SM_A_HI + swA);
        ldm4(al, smem_base + SM_A_LO + swA);
#pragma unroll
        for (int p = 0; p < 4; p++) {
            unsigned offB = (unsigned)(nh * 64 + p * 16 + nb_l) * 128u
                          + (unsigned)(kt * 16 + kqB) * 2u;
            unsigned swB = SW128(offB);
            unsigned bh[4], bl[4];
            ldm4(bh, smem_base + SM_B_HI + swB);
            ldm4(bl, smem_base + SM_B_LO + swB);
            mma_bf16(acc[p * 2],     ah, bh);
            mma_bf16(acc[p * 2 + 1], ah, bh + 2);
            mma_bf16(acc[p * 2],     al, bh);
            mma_bf16(acc[p * 2 + 1], al, bh + 2);
            mma_bf16(acc[p * 2],     ah, bl);
            mma_bf16(acc[p * 2 + 1], ah, bl + 2);
        }
    }
    __syncthreads();   // everyone done reading A/B before overlay

    // ---- spill D to shared: sWout[e][c], padded stride 132 ----
    float* sWout = reinterpret_cast<float*>(sm);
    {
        const int r0 = mi * 16 + (l >> 2);
#pragma unroll
        for (int nt = 0; nt < 8; nt++) {
            const int c = nh * 64 + nt * 8 + (l & 3) * 2;
            *reinterpret_cast<float2*>(sWout + r0 * WOUT_STRIDE + c)       = make_float2(acc[nt][0], acc[nt][1]);
            *reinterpret_cast<float2*>(sWout + (r0 + 8) * WOUT_STRIDE + c) = make_float2(acc[nt][2], acc[nt][3]);
        }
    }
    __syncthreads();

    // ---- tensor-product messages + scatter-add (4 threads/edge, 2 passes) ----
    const int le = t >> 2;
    const int p  = t & 3;
    const int e  = eBase + le;

    const int srcn = esrc[e];
    const int dstn = edst[e];
    float4 ea = *reinterpret_cast<const float4*>(eattr + (size_t)e * 4);
    const float es = ea.x, ev0 = ea.y, ev1 = ea.z, ev2 = ea.w;

    const float* feat = g_feat + (size_t)srcn * 128;
    const float* Wrow = sWout + le * WOUT_STRIDE;
    float* as = g_acc_s + (size_t)dstn * 64;
    float* av = g_acc_v + (size_t)dstn * 192;

#pragma unroll
    for (int h = 0; h < 2; h++) {
        const int m0 = p * 8 + h * 4;
        float4 se = *reinterpret_cast<const float4*>(feat + m0);
        float4 w0 = *reinterpret_cast<const float4*>(Wrow + m0);
        float4 w1 = *reinterpret_cast<const float4*>(Wrow + 32 + m0);
        float4 w2 = *reinterpret_cast<const float4*>(Wrow + 64 + m0);
        float4 w3 = *reinterpret_cast<const float4*>(Wrow + 96 + m0);
        float ve[12];
        *reinterpret_cast<float4*>(ve + 0) = *reinterpret_cast<const float4*>(feat + 32 + m0 * 3);
        *reinterpret_cast<float4*>(ve + 4) = *reinterpret_cast<const float4*>(feat + 32 + m0 * 3 + 4);
        *reinterpret_cast<float4*>(ve + 8) = *reinterpret_cast<const float4*>(feat + 32 + m0 * 3 + 8);

        red4(as + m0, w0.x * se.x * es, w0.y * se.y * es, w0.z * se.z * es, w0.w * se.w * es);

        float d0 = ve[0] * ev0 + ve[1]  * ev1 + ve[2]  * ev2;
        float d1 = ve[3] * ev0 + ve[4]  * ev1 + ve[5]  * ev2;
        float d2 = ve[6] * ev0 + ve[7]  * ev1 + ve[8]  * ev2;
        float d3 = ve[9] * ev0 + ve[10] * ev1 + ve[11] * ev2;
        red4(as + 32 + m0, w3.x * d0 * RSQRT3f, w3.y * d1 * RSQRT3f,
                           w3.z * d2 * RSQRT3f, w3.w * d3 * RSQRT3f);

        float a0 = w1.x * se.x, a1 = w1.y * se.y, a2 = w1.z * se.z, a3 = w1.w * se.w;
        float* pv = av + m0 * 3;
        red4(pv + 0, a0 * ev0, a0 * ev1, a0 * ev2, a1 * ev0);
        red4(pv + 4, a1 * ev1, a1 * ev2, a2 * ev0, a2 * ev1);
        red4(pv + 8, a2 * ev2, a3 * ev0, a3 * ev1, a3 * ev2);

        float b0 = w2.x * es, b1 = w2.y * es, b2 = w2.z * es, b3 = w2.w * es;
        float* qv = av + 96 + m0 * 3;
        red4(qv + 0, b0 * ve[0], b0 * ve[1], b0 * ve[2],  b1 * ve[3]);
        red4(qv + 4, b1 * ve[4], b1 * ve[5], b2 * ve[6],  b2 * ve[7]);
        red4(qv + 8, b2 * ve[8], b3 * ve[9], b3 * ve[10], b3 * ve[11]);
    }
}

// ============================================================
// node lin2 — transposed weights, float4 LDS
// ============================================================
__global__ __launch_bounds__(256) void node_lin2(
    const float* __restrict__ w2s,
    const float* __restrict__ w2v,
    float* __restrict__ out)
{
    __shared__ float sWsT[32 * 68];
    __shared__ float sWvT[32 * 68];
    __shared__ float sRow[8][256];

    int t = threadIdx.x;
    for (int i = t; i < 2048; i += 256) {
        int u = i >> 5, c = i & 31;
        sWsT[c * 68 + u] = w2s[i] * SCALE2f;
        sWvT[c * 68 + u] = w2v[i] * SCALE2f;
    }
    int warp = t >> 5, lane = t & 31;
    int n = blockIdx.x * 8 + warp;

    const float4* ap = reinterpret_cast<const float4*>(g_acc_s + (size_t)n * 64);
    const float4* vp = reinterpret_cast<const float4*>(g_acc_v + (size_t)n * 192);
    if (lane < 16)
        *reinterpret_cast<float4*>(&sRow[warp][lane * 4]) = ap[lane];
    *reinterpret_cast<float4*>(&sRow[warp][64 + lane * 4]) = vp[lane];
    if (lane < 16)
        *reinterpret_cast<float4*>(&sRow[warp][64 + 128 + lane * 4]) = vp[32 + lane];
    __syncthreads();

    const float* r = sRow[warp];
    const float* ws = sWsT + lane * 68;
    const float* wv = sWvT + lane * 68;
    float s = 0.f, v0 = 0.f, v1 = 0.f, v2 = 0.f;
#pragma unroll
    for (int u4 = 0; u4 < 64; u4 += 4) {
        float4 wsq = *reinterpret_cast<const float4*>(ws + u4);
        float4 wvq = *reinterpret_cast<const float4*>(wv + u4);
        float4 rs  = *reinterpret_cast<const float4*>(r + u4);
        float4 ra  = *reinterpret_cast<const float4*>(r + 64 + u4 * 3);
        float4 rb  = *reinterpret_cast<const float4*>(r + 64 + u4 * 3 + 4);
        float4 rc  = *reinterpret_cast<const float4*>(r + 64 + u4 * 3 + 8);
        s += rs.x * wsq.x + rs.y * wsq.y + rs.z * wsq.z + rs.w * wsq.w;
        v0 += ra.x * wvq.x; v1 += ra.y * wvq.x; v2 += ra.z * wvq.x;
        v0 += ra.w * wvq.y; v1 += rb.x * wvq.y; v2 += rb.y * wvq.y;
        v0 += rb.z * wvq.z; v1 += rb.w * wvq.z; v2 += rc.x * wvq.z;
        v0 += rc.y * wvq.w; v1 += rc.z * wvq.w; v2 += rc.w * wvq.w;
    }
    float* o = out + (size_t)n * 128;
    o[lane] = s;
    o[32 + lane * 3 + 0] = v0;
    o[32 + lane * 3 + 1] = v1;
    o[32 + lane * 3 + 2] = v2;
}

// ============================================================
// launch
// ============================================================
extern "C" void kernel_launch(void* const* d_in, const int* in_sizes, int n_in,
                              void* d_out, int out_size)
{
    const float* node_input = (const float*)d_in[0];
    const int*   esrc  = (const int*)d_in[2];
    const int*   edst  = (const int*)d_in[3];
    const float* eattr = (const float*)d_in[4];
    const float* escal = (const float*)d_in[5];
    const float* w1s   = (const float*)d_in[6];
    const float* w1v   = (const float*)d_in[7];
    const float* fw1   = (const float*)d_in[8];
    const float* fw2   = (const float*)d_in[9];
    const float* w2s   = (const float*)d_in[10];
    const float* w2v   = (const float*)d_in[11];
    float* out = (float*)d_out;

    zero_acc<<<2048, 256>>>();
    prep_w2t<<<16, 256>>>(fw2);
    node_lin1<<<NN / 8, 256>>>(node_input, w1s, w1v);

    cudaFuncSetAttribute(edge_kernel, cudaFuncAttributeMaxDynamicSharedMemorySize, SM_TOTAL);
    edge_kernel<<<NE / 64, 256, SM_TOTAL>>>(esrc, edst, eattr, escal, fw1);

    node_lin2<<<NN / 8, 256>>>(w2s, w2v, out);
}